// round 1
// baseline (speedup 1.0000x reference)
#include <cuda_runtime.h>
#include <math.h>

#define GS 96
#define GS2 (GS*GS)
#define NP (GS*GS*GS)          // 884736
#define NVIEW 8
#define HIM 256
#define WIM 256
#define IMPLANE (HIM*WIM)      // 65536

// latm scratch: 96^3 * 3 floats = 10.6 MB (device global, no allocation)
__device__ float g_latm[NP * 3];

// ---------------------------------------------------------------------------
// Kernel A: per (point) loop over views: project, bilinear sample, tiny MLP.
// Writes out_latent[(n*3+c)*NP + p], lat5[((n*NP+p)*3)+c], g_latm[p*3+c].
// ---------------------------------------------------------------------------
__global__ void __launch_bounds__(256) encode_kernel(
    const float* __restrict__ images,
    const float* __restrict__ poses,
    const float* __restrict__ focal,
    const float* __restrict__ cvec,
    const float* __restrict__ dw1, const float* __restrict__ db1,
    const float* __restrict__ dw2, const float* __restrict__ db2,
    const float* __restrict__ dw3, const float* __restrict__ db3,
    float* __restrict__ out_latent,
    float* __restrict__ lat5)
{
    __shared__ float sposes[NVIEW * 16];
    __shared__ float sw1[27], sb1[3], sw2[9], sb2[3], sw3[9], sb3[3];
    __shared__ float sf[3];   // f, cx2, cy2

    int tid = threadIdx.x;
    if (tid < NVIEW * 16) sposes[tid] = poses[tid];
    if (tid >= 128 && tid < 128 + 27) sw1[tid - 128] = dw1[tid - 128];
    int u = tid - 160;
    if (u >= 0 && u < 3)  sb1[u] = db1[u];
    if (u >= 3 && u < 12) sw2[u - 3] = dw2[u - 3];
    if (u >= 12 && u < 15) sb2[u - 12] = db2[u - 12];
    if (u >= 15 && u < 24) sw3[u - 15] = dw3[u - 15];
    if (u >= 24 && u < 27) sb3[u - 24] = db3[u - 24];
    if (u == 27) sf[0] = focal[0] * 0.5f;   // f = focal/stride, stride = 2
    if (u == 28) sf[1] = cvec[0] * 0.5f;    // cx2
    if (u == 29) sf[2] = cvec[1] * 0.5f;    // cy2
    __syncthreads();

    int p = blockIdx.x * 256 + tid;         // grid is exact: 884736 = 3456*256
    int iz = p % GS;
    int iy = (p / GS) % GS;
    int ix = p / GS2;
    float wxp = -1.0f + 2.0f * (float)ix / 95.0f;
    float wyp = -1.0f + 2.0f * (float)iy / 95.0f;
    float wzp = (float)iz / 95.0f;

    const float f   = sf[0];
    const float cx2 = sf[1];
    const float cy2 = sf[2];

    float acc0 = 0.f, acc1 = 0.f, acc2 = 0.f;

    #pragma unroll 1
    for (int n = 0; n < NVIEW; n++) {
        const float* Pn = sposes + n * 16;
        float dx = wxp - Pn[3];
        float dy = wyp - Pn[7];
        float dz = wzp - Pn[11];
        // cam_i = sum_j d_j * R[j][i],  R[j][i] = poses[n][j][i]
        float camx = dx * Pn[0] + dy * Pn[4] + dz * Pn[8];
        float camy = dx * Pn[1] + dy * Pn[5] + dz * Pn[9];
        float camz = dx * Pn[2] + dy * Pn[6] + dz * Pn[10];

        const float eps = 1e-9f;
        float ddx = dx + eps, ddy = dy + eps, ddz = dz + eps;
        float dn = sqrtf(ddx * ddx + ddy * ddy + ddz * ddz);
        float invdn = __fdividef(1.0f, dn);
        float dirx = dx * invdn, diry = dy * invdn, dirz = dz * invdn;

        float invz = __fdividef(1.0f, camz);
        float uvx =  camx * invz * f + cx2;
        float uvy = -camy * invz * f + cy2;
        float gxn = uvx * (2.0f / 127.0f) - 1.0f;
        float gyn = uvy * (2.0f / 127.0f) - 1.0f;

        bool maskz  = camz < 0.001f;
        bool inside = (fabsf(gxn) <= 1.0f) && (fabsf(gyn) <= 1.0f) && maskz;

        float l0 = 0.f, l1 = 0.f, l2 = 0.f;
        if (inside) {
            // grid_sample into full-res 256x256 feats (= images*0.5+0.5)
            float sx = (gxn + 1.0f) * 127.5f;   // in [0, 255]
            float sy = (gyn + 1.0f) * 127.5f;
            float x0f = floorf(sx), y0f = floorf(sy);
            float fx = sx - x0f, fy = sy - y0f;
            int x0 = (int)x0f, y0 = (int)y0f;
            int x1 = min(x0 + 1, WIM - 1);      // invalid corner always has w=0
            int y1 = min(y0 + 1, HIM - 1);
            float w00 = (1.f - fx) * (1.f - fy);
            float w01 = fx * (1.f - fy);
            float w10 = (1.f - fx) * fy;
            float w11 = fx * fy;
            int o00 = y0 * WIM + x0, o01 = y0 * WIM + x1;
            int o10 = y1 * WIM + x0, o11 = y1 * WIM + x1;
            const float* base = images + (size_t)n * 3 * IMPLANE;
            float lv[3];
            #pragma unroll
            for (int cch = 0; cch < 3; cch++) {
                const float* bc = base + cch * IMPLANE;
                float v00 = __ldg(bc + o00) * 0.5f + 0.5f;
                float v01 = __ldg(bc + o01) * 0.5f + 0.5f;
                float v10 = __ldg(bc + o10) * 0.5f + 0.5f;
                float v11 = __ldg(bc + o11) * 0.5f + 0.5f;
                lv[cch] = v00 * w00 + v01 * w01 + v10 * w10 + v11 * w11;
            }
            l0 = lv[0]; l1 = lv[1]; l2 = lv[2];
        }

        float mz = maskz ? 1.0f : 0.0f;
        dirx *= mz; diry *= mz; dirz *= mz;

        // tiny MLP: 9 -> 3 (relu) -> 3 (relu) -> 3
        float xin[9] = { l0, l1, l2, camx, camy, camz, dirx, diry, dirz };
        float h1[3], h2[3], h3[3];
        #pragma unroll
        for (int i = 0; i < 3; i++) {
            float s = sb1[i];
            #pragma unroll
            for (int j = 0; j < 9; j++) s += xin[j] * sw1[i * 9 + j];
            h1[i] = fmaxf(s, 0.0f);
        }
        #pragma unroll
        for (int i = 0; i < 3; i++) {
            float s = sb2[i];
            #pragma unroll
            for (int j = 0; j < 3; j++) s += h1[j] * sw2[i * 3 + j];
            h2[i] = fmaxf(s, 0.0f);
        }
        #pragma unroll
        for (int i = 0; i < 3; i++) {
            float s = sb3[i];
            #pragma unroll
            for (int j = 0; j < 3; j++) s += h2[j] * sw3[i * 3 + j];
            h3[i] = s;
        }

        // out_latent[n][c][p]
        out_latent[((size_t)n * 3 + 0) * NP + p] = l0;
        out_latent[((size_t)n * 3 + 1) * NP + p] = l1;
        out_latent[((size_t)n * 3 + 2) * NP + p] = l2;
        // lat5[n][p][c]
        size_t lbase = ((size_t)n * NP + p) * 3;
        lat5[lbase + 0] = h3[0];
        lat5[lbase + 1] = h3[1];
        lat5[lbase + 2] = h3[2];

        acc0 += h3[0]; acc1 += h3[1]; acc2 += h3[2];
    }

    g_latm[(size_t)p * 3 + 0] = acc0 * 0.125f;
    g_latm[(size_t)p * 3 + 1] = acc1 * 0.125f;
    g_latm[(size_t)p * 3 + 2] = acc2 * 0.125f;
}

// ---------------------------------------------------------------------------
// Kernel B: per-line softmax aggregation. One warp = one 96-element line.
// axis 0: softmax over x for fixed (y,z) -> scene_yz
// axis 1: softmax over y for fixed (x,z) -> scene_xz
// axis 2: softmax over z for fixed (x,y) -> scene_xy
// ---------------------------------------------------------------------------
__global__ void __launch_bounds__(256) agg_kernel(
    const float* __restrict__ ayz_w1, const float* __restrict__ ayz_b1,
    const float* __restrict__ ayz_w2, const float* __restrict__ ayz_b2,
    const float* __restrict__ axz_w1, const float* __restrict__ axz_b1,
    const float* __restrict__ axz_w2, const float* __restrict__ axz_b2,
    const float* __restrict__ axy_w1, const float* __restrict__ axy_b1,
    const float* __restrict__ axy_w2, const float* __restrict__ axy_b2,
    float* __restrict__ out)   // scenes at start of d_out
{
    int gwarp = (blockIdx.x * 256 + threadIdx.x) >> 5;
    int lane  = threadIdx.x & 31;
    int axis  = gwarp / (GS2);          // 9216 lines per axis
    int line  = gwarp % (GS2);
    int a = line / GS;
    int b = line % GS;

    const float* W1; const float* B1; const float* W2; const float* B2;
    if (axis == 0)      { W1 = ayz_w1; B1 = ayz_b1; W2 = ayz_w2; B2 = ayz_b2; }
    else if (axis == 1) { W1 = axz_w1; B1 = axz_b1; W2 = axz_w2; B2 = axz_b2; }
    else                { W1 = axy_w1; B1 = axy_b1; W2 = axy_w2; B2 = axy_b2; }

    float w1r[12], b1r[3], w2r[3], b2r;
    #pragma unroll
    for (int i = 0; i < 12; i++) w1r[i] = __ldg(W1 + i);
    #pragma unroll
    for (int i = 0; i < 3; i++)  b1r[i] = __ldg(B1 + i);
    #pragma unroll
    for (int i = 0; i < 3; i++)  w2r[i] = __ldg(W2 + i);
    b2r = __ldg(B2);

    float lm[3][3];   // [k][channel]
    float sc[3];
    #pragma unroll
    for (int k = 0; k < 3; k++) {
        int e = lane * 3 + k;   // 96 = 32*3 exact
        int p; float coord;
        if (axis == 0)      { p = (e * GS + a) * GS + b; coord = -1.0f + 2.0f * (float)e / 95.0f; }
        else if (axis == 1) { p = (a * GS + e) * GS + b; coord = -1.0f + 2.0f * (float)e / 95.0f; }
        else                { p = (a * GS + b) * GS + e; coord = (float)e / 95.0f; }
        float m0 = g_latm[(size_t)p * 3 + 0];
        float m1 = g_latm[(size_t)p * 3 + 1];
        float m2 = g_latm[(size_t)p * 3 + 2];
        lm[k][0] = m0; lm[k][1] = m1; lm[k][2] = m2;
        float s = b2r;
        #pragma unroll
        for (int i = 0; i < 3; i++) {
            float h = w1r[i * 4 + 0] * m0 + w1r[i * 4 + 1] * m1 +
                      w1r[i * 4 + 2] * m2 + w1r[i * 4 + 3] * coord + b1r[i];
            s += fmaxf(h, 0.0f) * w2r[i];
        }
        sc[k] = s;
    }

    // warp softmax over 96 values
    float m = fmaxf(sc[0], fmaxf(sc[1], sc[2]));
    #pragma unroll
    for (int off = 16; off > 0; off >>= 1)
        m = fmaxf(m, __shfl_xor_sync(0xffffffffu, m, off));
    float e0 = expf(sc[0] - m), e1 = expf(sc[1] - m), e2 = expf(sc[2] - m);
    float ssum = e0 + e1 + e2;
    #pragma unroll
    for (int off = 16; off > 0; off >>= 1)
        ssum += __shfl_xor_sync(0xffffffffu, ssum, off);
    float inv = __fdividef(1.0f, ssum);

    float fl[3];
    #pragma unroll
    for (int c = 0; c < 3; c++) {
        float acc = lm[0][c] * e0 + lm[1][c] * e1 + lm[2][c] * e2;
        #pragma unroll
        for (int off = 16; off > 0; off >>= 1)
            acc += __shfl_xor_sync(0xffffffffu, acc, off);
        fl[c] = acc * inv;
    }

    if (lane == 0) {
        // d_out layout: scene_xz (27648) | scene_xy (27648) | scene_yz (27648) | ...
        float* dst;
        if (axis == 0)      dst = out + 2 * 27648;   // scene_yz[c][y][z], a=y,b=z
        else if (axis == 1) dst = out + 0;           // scene_xz[c][x][z], a=x,b=z
        else                dst = out + 27648;       // scene_xy[c][x][y], a=x,b=y
        #pragma unroll
        for (int c = 0; c < 3; c++)
            dst[c * GS2 + a * GS + b] = fl[c];
    }
}

extern "C" void kernel_launch(void* const* d_in, const int* in_sizes, int n_in,
                              void* d_out, int out_size)
{
    const float* images = (const float*)d_in[0];
    const float* poses  = (const float*)d_in[1];
    const float* focal  = (const float*)d_in[2];
    const float* cvec   = (const float*)d_in[3];
    const float* dw1 = (const float*)d_in[4];
    const float* db1 = (const float*)d_in[5];
    const float* dw2 = (const float*)d_in[6];
    const float* db2 = (const float*)d_in[7];
    const float* dw3 = (const float*)d_in[8];
    const float* db3 = (const float*)d_in[9];
    const float* ayz_w1 = (const float*)d_in[10];
    const float* ayz_b1 = (const float*)d_in[11];
    const float* ayz_w2 = (const float*)d_in[12];
    const float* ayz_b2 = (const float*)d_in[13];
    const float* axz_w1 = (const float*)d_in[14];
    const float* axz_b1 = (const float*)d_in[15];
    const float* axz_w2 = (const float*)d_in[16];
    const float* axz_b2 = (const float*)d_in[17];
    const float* axy_w1 = (const float*)d_in[18];
    const float* axy_b1 = (const float*)d_in[19];
    const float* axy_w2 = (const float*)d_in[20];
    const float* axy_b2 = (const float*)d_in[21];

    float* out = (float*)d_out;
    // layout: scene_xz | scene_xy | scene_yz | out_latent | lat5
    float* out_latent = out + 3 * 27648;                    // 82944
    float* lat5       = out + 3 * 27648 + (size_t)NVIEW * 3 * NP;

    encode_kernel<<<NP / 256, 256>>>(images, poses, focal, cvec,
                                     dw1, db1, dw2, db2, dw3, db3,
                                     out_latent, lat5);

    // 3 axes * 9216 lines = 27648 warps; 8 warps/block -> 3456 blocks
    agg_kernel<<<3456, 256>>>(ayz_w1, ayz_b1, ayz_w2, ayz_b2,
                              axz_w1, axz_b1, axz_w2, axz_b2,
                              axy_w1, axy_b1, axy_w2, axy_b2,
                              out);
}

// round 2
// speedup vs baseline: 1.6366x; 1.6366x over previous
#include <cuda_runtime.h>
#include <math.h>

#define GS 96
#define GS2 (GS*GS)
#define NP (GS*GS*GS)          // 884736
#define NVIEW 8
#define HIM 256
#define WIM 256
#define IMPLANE (HIM*WIM)      // 65536

// Device scratch (no allocation allowed):
__device__ float4 g_latm4[NP];                   // 14.1 MB, latm per point (xyz + pad)
__device__ float4 g_imgf4[NVIEW * IMPLANE];      // 8 MB, interleaved (rgb*0.5+0.5, 0)

// ---------------------------------------------------------------------------
// Kernel 0: repack images [n][3][H][W] -> float4 [n][H*W] with 0.5x+0.5 applied
// ---------------------------------------------------------------------------
__global__ void __launch_bounds__(256) prepack_kernel(const float* __restrict__ images)
{
    int idx = blockIdx.x * 256 + threadIdx.x;     // 524288 total
    int n = idx >> 16;                            // / IMPLANE
    int o = idx & (IMPLANE - 1);
    const float* base = images + (size_t)n * 3 * IMPLANE + o;
    float4 v;
    v.x = __ldg(base)               * 0.5f + 0.5f;
    v.y = __ldg(base + IMPLANE)     * 0.5f + 0.5f;
    v.z = __ldg(base + 2 * IMPLANE) * 0.5f + 0.5f;
    v.w = 0.f;
    g_imgf4[idx] = v;
}

// ---------------------------------------------------------------------------
// Kernel A: per grid point, loop over views: project, bilinear sample, tiny MLP
// ---------------------------------------------------------------------------
__global__ void __launch_bounds__(256) encode_kernel(
    const float* __restrict__ poses,
    const float* __restrict__ focal,
    const float* __restrict__ cvec,
    const float* __restrict__ dw1, const float* __restrict__ db1,
    const float* __restrict__ dw2, const float* __restrict__ db2,
    const float* __restrict__ dw3, const float* __restrict__ db3,
    float* __restrict__ out_latent,
    float* __restrict__ lat5)
{
    __shared__ float sposes[NVIEW * 16];
    __shared__ float sw1[27], sb1[3], sw2[9], sb2[3], sw3[9], sb3[3];
    __shared__ float sf[3];   // f, cx2, cy2

    int tid = threadIdx.x;
    if (tid < NVIEW * 16) sposes[tid] = poses[tid];
    if (tid >= 128 && tid < 128 + 27) sw1[tid - 128] = dw1[tid - 128];
    int u = tid - 160;
    if (u >= 0 && u < 3)  sb1[u] = db1[u];
    if (u >= 3 && u < 12) sw2[u - 3] = dw2[u - 3];
    if (u >= 12 && u < 15) sb2[u - 12] = db2[u - 12];
    if (u >= 15 && u < 24) sw3[u - 15] = dw3[u - 15];
    if (u >= 24 && u < 27) sb3[u - 24] = db3[u - 24];
    if (u == 27) sf[0] = focal[0] * 0.5f;   // f = focal/stride, stride = 2
    if (u == 28) sf[1] = cvec[0] * 0.5f;    // cx2
    if (u == 29) sf[2] = cvec[1] * 0.5f;    // cy2
    __syncthreads();

    int p = blockIdx.x * 256 + tid;         // 884736 = 3456*256 exact
    int iz = p % GS;
    int iy = (p / GS) % GS;
    int ix = p / GS2;
    float wxp = -1.0f + 2.0f * (float)ix / 95.0f;
    float wyp = -1.0f + 2.0f * (float)iy / 95.0f;
    float wzp = (float)iz / 95.0f;

    const float f   = sf[0];
    const float cx2 = sf[1];
    const float cy2 = sf[2];

    float acc0 = 0.f, acc1 = 0.f, acc2 = 0.f;

    #pragma unroll 2
    for (int n = 0; n < NVIEW; n++) {
        const float* Pn = sposes + n * 16;
        float dx = wxp - Pn[3];
        float dy = wyp - Pn[7];
        float dz = wzp - Pn[11];
        float camx = dx * Pn[0] + dy * Pn[4] + dz * Pn[8];
        float camy = dx * Pn[1] + dy * Pn[5] + dz * Pn[9];
        float camz = dx * Pn[2] + dy * Pn[6] + dz * Pn[10];

        const float eps = 1e-9f;
        float ddx = dx + eps, ddy = dy + eps, ddz = dz + eps;
        float dn = sqrtf(ddx * ddx + ddy * ddy + ddz * ddz);
        float invdn = __fdividef(1.0f, dn);
        float dirx = dx * invdn, diry = dy * invdn, dirz = dz * invdn;

        float invz = __fdividef(1.0f, camz);
        float uvx =  camx * invz * f + cx2;
        float uvy = -camy * invz * f + cy2;
        float gxn = uvx * (2.0f / 127.0f) - 1.0f;
        float gyn = uvy * (2.0f / 127.0f) - 1.0f;

        bool maskz  = camz < 0.001f;
        bool inside = (fabsf(gxn) <= 1.0f) && (fabsf(gyn) <= 1.0f) && maskz;

        float l0 = 0.f, l1 = 0.f, l2 = 0.f;
        if (inside) {
            float sx = (gxn + 1.0f) * 127.5f;   // in [0, 255]
            float sy = (gyn + 1.0f) * 127.5f;
            float x0f = floorf(sx), y0f = floorf(sy);
            float fx = sx - x0f, fy = sy - y0f;
            int x0 = (int)x0f, y0 = (int)y0f;
            int x1 = min(x0 + 1, WIM - 1);      // invalid corner always has w=0
            int y1 = min(y0 + 1, HIM - 1);
            float w00 = (1.f - fx) * (1.f - fy);
            float w01 = fx * (1.f - fy);
            float w10 = (1.f - fx) * fy;
            float w11 = fx * fy;
            const float4* base = g_imgf4 + (size_t)n * IMPLANE;
            float4 v00 = __ldg(base + (y0 << 8) + x0);
            float4 v01 = __ldg(base + (y0 << 8) + x1);
            float4 v10 = __ldg(base + (y1 << 8) + x0);
            float4 v11 = __ldg(base + (y1 << 8) + x1);
            l0 = v00.x * w00 + v01.x * w01 + v10.x * w10 + v11.x * w11;
            l1 = v00.y * w00 + v01.y * w01 + v10.y * w10 + v11.y * w11;
            l2 = v00.z * w00 + v01.z * w01 + v10.z * w10 + v11.z * w11;
        }

        float mz = maskz ? 1.0f : 0.0f;
        dirx *= mz; diry *= mz; dirz *= mz;

        // tiny MLP: 9 -> 3 (relu) -> 3 (relu) -> 3
        float xin[9] = { l0, l1, l2, camx, camy, camz, dirx, diry, dirz };
        float h1[3], h2[3], h3[3];
        #pragma unroll
        for (int i = 0; i < 3; i++) {
            float s = sb1[i];
            #pragma unroll
            for (int j = 0; j < 9; j++) s += xin[j] * sw1[i * 9 + j];
            h1[i] = fmaxf(s, 0.0f);
        }
        #pragma unroll
        for (int i = 0; i < 3; i++) {
            float s = sb2[i];
            #pragma unroll
            for (int j = 0; j < 3; j++) s += h1[j] * sw2[i * 3 + j];
            h2[i] = fmaxf(s, 0.0f);
        }
        #pragma unroll
        for (int i = 0; i < 3; i++) {
            float s = sb3[i];
            #pragma unroll
            for (int j = 0; j < 3; j++) s += h2[j] * sw3[i * 3 + j];
            h3[i] = s;
        }

        // out_latent[n][c][p]
        out_latent[((size_t)n * 3 + 0) * NP + p] = l0;
        out_latent[((size_t)n * 3 + 1) * NP + p] = l1;
        out_latent[((size_t)n * 3 + 2) * NP + p] = l2;
        // lat5[n][p][c]
        size_t lbase = ((size_t)n * NP + p) * 3;
        lat5[lbase + 0] = h3[0];
        lat5[lbase + 1] = h3[1];
        lat5[lbase + 2] = h3[2];

        acc0 += h3[0]; acc1 += h3[1]; acc2 += h3[2];
    }

    g_latm4[p] = make_float4(acc0 * 0.125f, acc1 * 0.125f, acc2 * 0.125f, 0.f);
}

// ---------------------------------------------------------------------------
// Kernel B: per-line softmax aggregation. One warp = one 96-element line.
// ---------------------------------------------------------------------------
__global__ void __launch_bounds__(256) agg_kernel(
    const float* __restrict__ ayz_w1, const float* __restrict__ ayz_b1,
    const float* __restrict__ ayz_w2, const float* __restrict__ ayz_b2,
    const float* __restrict__ axz_w1, const float* __restrict__ axz_b1,
    const float* __restrict__ axz_w2, const float* __restrict__ axz_b2,
    const float* __restrict__ axy_w1, const float* __restrict__ axy_b1,
    const float* __restrict__ axy_w2, const float* __restrict__ axy_b2,
    float* __restrict__ out)   // scenes at start of d_out
{
    int gwarp = (blockIdx.x * 256 + threadIdx.x) >> 5;
    int lane  = threadIdx.x & 31;
    int axis  = gwarp / (GS2);          // 9216 lines per axis
    int line  = gwarp % (GS2);
    int a = line / GS;
    int b = line % GS;

    const float* W1; const float* B1; const float* W2; const float* B2;
    if (axis == 0)      { W1 = ayz_w1; B1 = ayz_b1; W2 = ayz_w2; B2 = ayz_b2; }
    else if (axis == 1) { W1 = axz_w1; B1 = axz_b1; W2 = axz_w2; B2 = axz_b2; }
    else                { W1 = axy_w1; B1 = axy_b1; W2 = axy_w2; B2 = axy_b2; }

    float w1r[12], b1r[3], w2r[3], b2r;
    #pragma unroll
    for (int i = 0; i < 12; i++) w1r[i] = __ldg(W1 + i);
    #pragma unroll
    for (int i = 0; i < 3; i++)  b1r[i] = __ldg(B1 + i);
    #pragma unroll
    for (int i = 0; i < 3; i++)  w2r[i] = __ldg(W2 + i);
    b2r = __ldg(B2);

    float lm[3][3];   // [k][channel]
    float sc[3];
    #pragma unroll
    for (int k = 0; k < 3; k++) {
        int e = lane * 3 + k;   // 96 = 32*3 exact
        int p; float coord;
        if (axis == 0)      { p = (e * GS + a) * GS + b; coord = -1.0f + 2.0f * (float)e / 95.0f; }
        else if (axis == 1) { p = (a * GS + e) * GS + b; coord = -1.0f + 2.0f * (float)e / 95.0f; }
        else                { p = (a * GS + b) * GS + e; coord = (float)e / 95.0f; }
        float4 m = __ldg(&g_latm4[p]);
        lm[k][0] = m.x; lm[k][1] = m.y; lm[k][2] = m.z;
        float s = b2r;
        #pragma unroll
        for (int i = 0; i < 3; i++) {
            float h = w1r[i * 4 + 0] * m.x + w1r[i * 4 + 1] * m.y +
                      w1r[i * 4 + 2] * m.z + w1r[i * 4 + 3] * coord + b1r[i];
            s += fmaxf(h, 0.0f) * w2r[i];
        }
        sc[k] = s;
    }

    // warp softmax over 96 values
    float m = fmaxf(sc[0], fmaxf(sc[1], sc[2]));
    #pragma unroll
    for (int off = 16; off > 0; off >>= 1)
        m = fmaxf(m, __shfl_xor_sync(0xffffffffu, m, off));
    float e0 = expf(sc[0] - m), e1 = expf(sc[1] - m), e2 = expf(sc[2] - m);
    float ssum = e0 + e1 + e2;
    #pragma unroll
    for (int off = 16; off > 0; off >>= 1)
        ssum += __shfl_xor_sync(0xffffffffu, ssum, off);
    float inv = __fdividef(1.0f, ssum);

    float fl[3];
    #pragma unroll
    for (int c = 0; c < 3; c++) {
        float acc = lm[0][c] * e0 + lm[1][c] * e1 + lm[2][c] * e2;
        #pragma unroll
        for (int off = 16; off > 0; off >>= 1)
            acc += __shfl_xor_sync(0xffffffffu, acc, off);
        fl[c] = acc * inv;
    }

    if (lane == 0) {
        float* dst;
        if (axis == 0)      dst = out + 2 * 27648;   // scene_yz[c][y][z]
        else if (axis == 1) dst = out + 0;           // scene_xz[c][x][z]
        else                dst = out + 27648;       // scene_xy[c][x][y]
        #pragma unroll
        for (int c = 0; c < 3; c++)
            dst[c * GS2 + a * GS + b] = fl[c];
    }
}

extern "C" void kernel_launch(void* const* d_in, const int* in_sizes, int n_in,
                              void* d_out, int out_size)
{
    const float* images = (const float*)d_in[0];
    const float* poses  = (const float*)d_in[1];
    const float* focal  = (const float*)d_in[2];
    const float* cvec   = (const float*)d_in[3];
    const float* dw1 = (const float*)d_in[4];
    const float* db1 = (const float*)d_in[5];
    const float* dw2 = (const float*)d_in[6];
    const float* db2 = (const float*)d_in[7];
    const float* dw3 = (const float*)d_in[8];
    const float* db3 = (const float*)d_in[9];
    const float* ayz_w1 = (const float*)d_in[10];
    const float* ayz_b1 = (const float*)d_in[11];
    const float* ayz_w2 = (const float*)d_in[12];
    const float* ayz_b2 = (const float*)d_in[13];
    const float* axz_w1 = (const float*)d_in[14];
    const float* axz_b1 = (const float*)d_in[15];
    const float* axz_w2 = (const float*)d_in[16];
    const float* axz_b2 = (const float*)d_in[17];
    const float* axy_w1 = (const float*)d_in[18];
    const float* axy_b1 = (const float*)d_in[19];
    const float* axy_w2 = (const float*)d_in[20];
    const float* axy_b2 = (const float*)d_in[21];

    float* out = (float*)d_out;
    // layout: scene_xz | scene_xy | scene_yz | out_latent | lat5
    float* out_latent = out + 3 * 27648;
    float* lat5       = out + 3 * 27648 + (size_t)NVIEW * 3 * NP;

    prepack_kernel<<<(NVIEW * IMPLANE) / 256, 256>>>(images);

    encode_kernel<<<NP / 256, 256>>>(poses, focal, cvec,
                                     dw1, db1, dw2, db2, dw3, db3,
                                     out_latent, lat5);

    agg_kernel<<<3456, 256>>>(ayz_w1, ayz_b1, ayz_w2, ayz_b2,
                              axz_w1, axz_b1, axz_w2, axz_b2,
                              axy_w1, axy_b1, axy_w2, axy_b2,
                              out);
}

// round 4
// speedup vs baseline: 1.6939x; 1.0350x over previous
#include <cuda_runtime.h>
#include <math.h>

#define GS 96
#define GS2 (GS*GS)
#define NP (GS*GS*GS)          // 884736
#define NVIEW 8
#define HIM 256
#define WIM 256
#define IMPLANE (HIM*WIM)      // 65536

// Device scratch (no allocation allowed):
__device__ float4 g_latm4[NP];                   // 14.1 MB
__device__ float4 g_imgf4[NVIEW * IMPLANE];      // 8 MB, (rgb*0.5+0.5, 0)

// ---------------------------------------------------------------------------
// Kernel 0: repack images [n][3][H][W] -> float4 [n][H*W], 4 pixels per thread
// ---------------------------------------------------------------------------
__global__ void __launch_bounds__(256) prepack_kernel(const float* __restrict__ images)
{
    int tid = threadIdx.x;
    int base = blockIdx.x * 1024;                 // 512 blocks * 1024 px = 524288
    #pragma unroll
    for (int k = 0; k < 4; k++) {
        int pk = base + k * 256 + tid;
        int n = pk >> 16;
        int o = pk & (IMPLANE - 1);
        const float* bp = images + (size_t)n * 3 * IMPLANE + o;
        float4 v;
        v.x = __ldg(bp)               * 0.5f + 0.5f;
        v.y = __ldg(bp + IMPLANE)     * 0.5f + 0.5f;
        v.z = __ldg(bp + 2 * IMPLANE) * 0.5f + 0.5f;
        v.w = 0.f;
        g_imgf4[pk] = v;
    }
}

// ---------------------------------------------------------------------------
// Kernel A: per grid point, loop over views: project, bilinear sample, tiny MLP
// ---------------------------------------------------------------------------
__global__ void __launch_bounds__(256) encode_kernel(
    const float* __restrict__ poses,
    const float* __restrict__ focal,
    const float* __restrict__ cvec,
    const float* __restrict__ dw1, const float* __restrict__ db1,
    const float* __restrict__ dw2, const float* __restrict__ db2,
    const float* __restrict__ dw3, const float* __restrict__ db3,
    float* __restrict__ out_latent,
    float* __restrict__ lat5)
{
    __shared__ float sposes[NVIEW * 16];
    __shared__ float sw1[27], sb1[3], sw2[9], sb2[3], sw3[9], sb3[3];
    __shared__ float sf[3];
    __shared__ float s_lat5[256 * 3];

    int tid = threadIdx.x;
    if (tid < NVIEW * 16) sposes[tid] = poses[tid];
    if (tid >= 128 && tid < 128 + 27) sw1[tid - 128] = dw1[tid - 128];
    int u = tid - 160;
    if (u >= 0 && u < 3)  sb1[u] = db1[u];
    if (u >= 3 && u < 12) sw2[u - 3] = dw2[u - 3];
    if (u >= 12 && u < 15) sb2[u - 12] = db2[u - 12];
    if (u >= 15 && u < 24) sw3[u - 15] = dw3[u - 15];
    if (u >= 24 && u < 27) sb3[u - 24] = db3[u - 24];
    if (u == 27) sf[0] = focal[0] * 0.5f;
    if (u == 28) sf[1] = cvec[0] * 0.5f;
    if (u == 29) sf[2] = cvec[1] * 0.5f;
    __syncthreads();

    int p = blockIdx.x * 256 + tid;         // 884736 = 3456*256 exact
    int iz = p % GS;
    int iy = (p / GS) % GS;
    int ix = p / GS2;
    float wxp = -1.0f + 2.0f * (float)ix / 95.0f;
    float wyp = -1.0f + 2.0f * (float)iy / 95.0f;
    float wzp = (float)iz / 95.0f;

    const float f   = sf[0];
    const float cx2 = sf[1];
    const float cy2 = sf[2];

    float acc0 = 0.f, acc1 = 0.f, acc2 = 0.f;

    #pragma unroll 2
    for (int n = 0; n < NVIEW; n++) {
        const float* Pn = sposes + n * 16;
        float dx = wxp - Pn[3];
        float dy = wyp - Pn[7];
        float dz = wzp - Pn[11];
        float camx = dx * Pn[0] + dy * Pn[4] + dz * Pn[8];
        float camy = dx * Pn[1] + dy * Pn[5] + dz * Pn[9];
        float camz = dx * Pn[2] + dy * Pn[6] + dz * Pn[10];

        const float eps = 1e-9f;
        float ddx = dx + eps, ddy = dy + eps, ddz = dz + eps;
        float dn = sqrtf(ddx * ddx + ddy * ddy + ddz * ddz);
        float invdn = __fdividef(1.0f, dn);
        float dirx = dx * invdn, diry = dy * invdn, dirz = dz * invdn;

        float invz = __fdividef(1.0f, camz);
        float uvx =  camx * invz * f + cx2;
        float uvy = -camy * invz * f + cy2;
        float gxn = uvx * (2.0f / 127.0f) - 1.0f;
        float gyn = uvy * (2.0f / 127.0f) - 1.0f;

        bool maskz  = camz < 0.001f;
        bool inside = (fabsf(gxn) <= 1.0f) && (fabsf(gyn) <= 1.0f) && maskz;

        float l0 = 0.f, l1 = 0.f, l2 = 0.f;
        if (inside) {
            float sx = (gxn + 1.0f) * 127.5f;
            float sy = (gyn + 1.0f) * 127.5f;
            float x0f = floorf(sx), y0f = floorf(sy);
            float fx = sx - x0f, fy = sy - y0f;
            int x0 = (int)x0f, y0 = (int)y0f;
            int x1 = min(x0 + 1, WIM - 1);
            int y1 = min(y0 + 1, HIM - 1);
            float w00 = (1.f - fx) * (1.f - fy);
            float w01 = fx * (1.f - fy);
            float w10 = (1.f - fx) * fy;
            float w11 = fx * fy;
            const float4* base = g_imgf4 + (size_t)n * IMPLANE;
            float4 v00 = __ldg(base + (y0 << 8) + x0);
            float4 v01 = __ldg(base + (y0 << 8) + x1);
            float4 v10 = __ldg(base + (y1 << 8) + x0);
            float4 v11 = __ldg(base + (y1 << 8) + x1);
            l0 = v00.x * w00 + v01.x * w01 + v10.x * w10 + v11.x * w11;
            l1 = v00.y * w00 + v01.y * w01 + v10.y * w10 + v11.y * w11;
            l2 = v00.z * w00 + v01.z * w01 + v10.z * w10 + v11.z * w11;
        }

        float mz = maskz ? 1.0f : 0.0f;
        dirx *= mz; diry *= mz; dirz *= mz;

        float xin[9] = { l0, l1, l2, camx, camy, camz, dirx, diry, dirz };
        float h1[3], h2[3], h3[3];
        #pragma unroll
        for (int i = 0; i < 3; i++) {
            float s = sb1[i];
            #pragma unroll
            for (int j = 0; j < 9; j++) s += xin[j] * sw1[i * 9 + j];
            h1[i] = fmaxf(s, 0.0f);
        }
        #pragma unroll
        for (int i = 0; i < 3; i++) {
            float s = sb2[i];
            #pragma unroll
            for (int j = 0; j < 3; j++) s += h1[j] * sw2[i * 3 + j];
            h2[i] = fmaxf(s, 0.0f);
        }
        #pragma unroll
        for (int i = 0; i < 3; i++) {
            float s = sb3[i];
            #pragma unroll
            for (int j = 0; j < 3; j++) s += h2[j] * sw3[i * 3 + j];
            h3[i] = s;
        }

        // out_latent[n][c][p] — coalesced direct
        out_latent[((size_t)n * 3 + 0) * NP + p] = l0;
        out_latent[((size_t)n * 3 + 1) * NP + p] = l1;
        out_latent[((size_t)n * 3 + 2) * NP + p] = l2;

        // lat5[n][p][c] via smem transpose -> 3 coalesced stores
        s_lat5[tid * 3 + 0] = h3[0];
        s_lat5[tid * 3 + 1] = h3[1];
        s_lat5[tid * 3 + 2] = h3[2];
        __syncthreads();
        {
            float* dst = lat5 + (size_t)n * NP * 3 + (size_t)blockIdx.x * 768;
            dst[tid]       = s_lat5[tid];
            dst[tid + 256] = s_lat5[tid + 256];
            dst[tid + 512] = s_lat5[tid + 512];
        }
        __syncthreads();

        acc0 += h3[0]; acc1 += h3[1]; acc2 += h3[2];
    }

    g_latm4[p] = make_float4(acc0 * 0.125f, acc1 * 0.125f, acc2 * 0.125f, 0.f);
}

// ---------------------------------------------------------------------------
// Kernel B: softmax aggregation.
// Blocks [0,72): axes 0/1 — warp = 32 z-columns (lane = z), serial online
//                softmax over the axis, coalesced float4 loads.
// Blocks [72,1224): axis 2 — warp per line (z-contiguous).
// ---------------------------------------------------------------------------
__global__ void __launch_bounds__(256) agg_kernel(
    const float* __restrict__ ayz_w1, const float* __restrict__ ayz_b1,
    const float* __restrict__ ayz_w2, const float* __restrict__ ayz_b2,
    const float* __restrict__ axz_w1, const float* __restrict__ axz_b1,
    const float* __restrict__ axz_w2, const float* __restrict__ axz_b2,
    const float* __restrict__ axy_w1, const float* __restrict__ axy_b1,
    const float* __restrict__ axy_w2, const float* __restrict__ axy_b2,
    float* __restrict__ out)
{
    int lane = threadIdx.x & 31;
    int wib  = threadIdx.x >> 5;

    if (blockIdx.x < 72) {
        // ---- axes 0 (over x, ayz, scene_yz) and 1 (over y, axz, scene_xz) ----
        int gw = blockIdx.x * 8 + wib;        // 0..575
        int axis = gw / 288;                  // 0 or 1
        int idx  = gw % 288;
        int a    = idx / 3;                   // y (axis0) or x (axis1)
        int z    = (idx % 3) * 32 + lane;

        const float* W1; const float* B1; const float* W2; const float* B2;
        if (axis == 0) { W1 = ayz_w1; B1 = ayz_b1; W2 = ayz_w2; B2 = ayz_b2; }
        else           { W1 = axz_w1; B1 = axz_b1; W2 = axz_w2; B2 = axz_b2; }

        float w1r[12], b1r[3], w2r[3], b2r;
        #pragma unroll
        for (int i = 0; i < 12; i++) w1r[i] = __ldg(W1 + i);
        #pragma unroll
        for (int i = 0; i < 3; i++)  b1r[i] = __ldg(B1 + i);
        #pragma unroll
        for (int i = 0; i < 3; i++)  w2r[i] = __ldg(W2 + i);
        b2r = __ldg(B2);

        float M = -1e30f, D = 0.f;
        float ac0 = 0.f, ac1 = 0.f, ac2 = 0.f;

        #pragma unroll 1
        for (int e0 = 0; e0 < GS; e0 += 4) {
            float4 mv[4]; float sc[4];
            #pragma unroll
            for (int k = 0; k < 4; k++) {
                int e = e0 + k;
                int pp = (axis == 0) ? (e * GS + a) * GS + z
                                     : (a * GS + e) * GS + z;
                mv[k] = __ldg(&g_latm4[pp]);
            }
            #pragma unroll
            for (int k = 0; k < 4; k++) {
                int e = e0 + k;
                float coord = -1.0f + 2.0f * (float)e / 95.0f;
                float s = b2r;
                #pragma unroll
                for (int i = 0; i < 3; i++) {
                    float h = w1r[i*4+0] * mv[k].x + w1r[i*4+1] * mv[k].y +
                              w1r[i*4+2] * mv[k].z + w1r[i*4+3] * coord + b1r[i];
                    s += fmaxf(h, 0.0f) * w2r[i];
                }
                sc[k] = s;
            }
            float bm = fmaxf(fmaxf(sc[0], sc[1]), fmaxf(sc[2], sc[3]));
            float Mn = fmaxf(M, bm);
            float scale = __expf(M - Mn);
            float w0 = __expf(sc[0] - Mn), w1 = __expf(sc[1] - Mn);
            float w2 = __expf(sc[2] - Mn), w3 = __expf(sc[3] - Mn);
            D   = D   * scale + (w0 + w1 + w2 + w3);
            ac0 = ac0 * scale + w0*mv[0].x + w1*mv[1].x + w2*mv[2].x + w3*mv[3].x;
            ac1 = ac1 * scale + w0*mv[0].y + w1*mv[1].y + w2*mv[2].y + w3*mv[3].y;
            ac2 = ac2 * scale + w0*mv[0].z + w1*mv[1].z + w2*mv[2].z + w3*mv[3].z;
            M = Mn;
        }

        float inv = __fdividef(1.0f, D);
        float* dst = out + (axis == 0 ? 2 * 27648 : 0);
        dst[0 * GS2 + a * GS + z] = ac0 * inv;
        dst[1 * GS2 + a * GS + z] = ac1 * inv;
        dst[2 * GS2 + a * GS + z] = ac2 * inv;
    } else {
        // ---- axis 2 (over z, axy, scene_xy): warp per line, 9216 lines ----
        int gw2 = (blockIdx.x - 72) * 8 + wib;    // 0..9215 (1152 blocks)
        int a = gw2 / GS;     // x
        int b = gw2 % GS;     // y

        float w1r[12], b1r[3], w2r[3], b2r;
        #pragma unroll
        for (int i = 0; i < 12; i++) w1r[i] = __ldg(axy_w1 + i);
        #pragma unroll
        for (int i = 0; i < 3; i++)  b1r[i] = __ldg(axy_b1 + i);
        #pragma unroll
        for (int i = 0; i < 3; i++)  w2r[i] = __ldg(axy_w2 + i);
        b2r = __ldg(axy_b2);

        float lm[3][3];
        float sc[3];
        int pbase = (a * GS + b) * GS;
        #pragma unroll
        for (int k = 0; k < 3; k++) {
            int e = lane * 3 + k;
            float coord = (float)e / 95.0f;
            float4 m = __ldg(&g_latm4[pbase + e]);
            lm[k][0] = m.x; lm[k][1] = m.y; lm[k][2] = m.z;
            float s = b2r;
            #pragma unroll
            for (int i = 0; i < 3; i++) {
                float h = w1r[i*4+0] * m.x + w1r[i*4+1] * m.y +
                          w1r[i*4+2] * m.z + w1r[i*4+3] * coord + b1r[i];
                s += fmaxf(h, 0.0f) * w2r[i];
            }
            sc[k] = s;
        }

        float m = fmaxf(sc[0], fmaxf(sc[1], sc[2]));
        #pragma unroll
        for (int off = 16; off > 0; off >>= 1)
            m = fmaxf(m, __shfl_xor_sync(0xffffffffu, m, off));
        float e0 = __expf(sc[0] - m), e1 = __expf(sc[1] - m), e2 = __expf(sc[2] - m);
        float ssum = e0 + e1 + e2;
        #pragma unroll
        for (int off = 16; off > 0; off >>= 1)
            ssum += __shfl_xor_sync(0xffffffffu, ssum, off);
        float inv = __fdividef(1.0f, ssum);

        float fl[3];
        #pragma unroll
        for (int c = 0; c < 3; c++) {
            float acc = lm[0][c] * e0 + lm[1][c] * e1 + lm[2][c] * e2;
            #pragma unroll
            for (int off = 16; off > 0; off >>= 1)
                acc += __shfl_xor_sync(0xffffffffu, acc, off);
            fl[c] = acc * inv;
        }

        if (lane == 0) {
            float* dst = out + 27648;   // scene_xy[c][x][y]
            #pragma unroll
            for (int c = 0; c < 3; c++)
                dst[c * GS2 + a * GS + b] = fl[c];
        }
    }
}

extern "C" void kernel_launch(void* const* d_in, const int* in_sizes, int n_in,
                              void* d_out, int out_size)
{
    const float* images = (const float*)d_in[0];
    const float* poses  = (const float*)d_in[1];
    const float* focal  = (const float*)d_in[2];
    const float* cvec   = (const float*)d_in[3];
    const float* dw1 = (const float*)d_in[4];
    const float* db1 = (const float*)d_in[5];
    const float* dw2 = (const float*)d_in[6];
    const float* db2 = (const float*)d_in[7];
    const float* dw3 = (const float*)d_in[8];
    const float* db3 = (const float*)d_in[9];
    const float* ayz_w1 = (const float*)d_in[10];
    const float* ayz_b1 = (const float*)d_in[11];
    const float* ayz_w2 = (const float*)d_in[12];
    const float* ayz_b2 = (const float*)d_in[13];
    const float* axz_w1 = (const float*)d_in[14];
    const float* axz_b1 = (const float*)d_in[15];
    const float* axz_w2 = (const float*)d_in[16];
    const float* axz_b2 = (const float*)d_in[17];
    const float* axy_w1 = (const float*)d_in[18];
    const float* axy_b1 = (const float*)d_in[19];
    const float* axy_w2 = (const float*)d_in[20];
    const float* axy_b2 = (const float*)d_in[21];

    float* out = (float*)d_out;
    float* out_latent = out + 3 * 27648;
    float* lat5       = out + 3 * 27648 + (size_t)NVIEW * 3 * NP;

    prepack_kernel<<<512, 256>>>(images);

    encode_kernel<<<NP / 256, 256>>>(poses, focal, cvec,
                                     dw1, db1, dw2, db2, dw3, db3,
                                     out_latent, lat5);

    // 72 blocks for axes 0/1 (576 warps) + 1152 blocks for axis 2 (9216 warps)
    agg_kernel<<<1224, 256>>>(ayz_w1, ayz_b1, ayz_w2, ayz_b2,
                              axz_w1, axz_b1, axz_w2, axz_b2,
                              axy_w1, axy_b1, axy_w2, axy_b2,
                              out);
}